// round 1
// baseline (speedup 1.0000x reference)
#include <cuda_runtime.h>

#define BN 32
#define VN 2
#define JN 17
#define HN 128
#define WN 128
#define HW (HN * WN)
#define NMAPS (BN * VN * JN)      // 1088
#define NFUSE (BN * JN)           // 544
#define IMG2_ELEMS (BN * VN * 2 * JN)  // 2176
#define INV_T 20.0f
#define EPSV 1e-12f

__device__ float g_maxv[NMAPS];
__device__ float g_x[NMAPS];
__device__ float g_y[NMAPS];
__device__ float g_w[NMAPS];

// ---------------- online softmax helpers ----------------

__device__ __forceinline__ void online_upd(float v, float wx, float hy,
                                           float& m, float& s, float& sx, float& sy) {
    if (v > m) {
        float sc = __expf((m - v) * INV_T);
        s  = s  * sc + 1.0f;
        sx = sx * sc + wx;
        sy = sy * sc + hy;
        m = v;
    } else {
        float e = __expf((v - m) * INV_T);
        s  += e;
        sx += e * wx;
        sy += e * hy;
    }
}

__device__ __forceinline__ void combine(float& m, float& s, float& sx, float& sy,
                                        float m2, float s2, float sx2, float sy2) {
    if (m2 > m) {
        float sc = __expf((m - m2) * INV_T);
        s  = s  * sc + s2;
        sx = sx * sc + sx2;
        sy = sy * sc + sy2;
        m = m2;
    } else {
        float sc = __expf((m2 - m) * INV_T);
        s  += s2  * sc;
        sx += sx2 * sc;
        sy += sy2 * sc;
    }
}

// ---------------- kernel 1: per-map soft-argmax stats ----------------

__global__ void stats_kernel(const float* __restrict__ hms) {
    int map = blockIdx.x;           // bv*17 + j
    int t = threadIdx.x;            // 256 threads
    const float4* src = (const float4*)(hms + (size_t)map * HW);

    float m = -1e30f, s = 0.f, sx = 0.f, sy = 0.f;

#pragma unroll
    for (int i = 0; i < 16; i++) {
        int i4 = t + i * 256;
        float4 v = src[i4];
        int base = i4 * 4;
        float hy = (float)(base >> 7);
        float wx = (float)(base & 127);
        online_upd(v.x, wx,        hy, m, s, sx, sy);
        online_upd(v.y, wx + 1.f,  hy, m, s, sx, sy);
        online_upd(v.z, wx + 2.f,  hy, m, s, sx, sy);
        online_upd(v.w, wx + 3.f,  hy, m, s, sx, sy);
    }

    __shared__ float sm[256], ss[256], ssx[256], ssy[256];
    sm[t] = m; ss[t] = s; ssx[t] = sx; ssy[t] = sy;
    __syncthreads();
    for (int off = 128; off; off >>= 1) {
        if (t < off)
            combine(sm[t], ss[t], ssx[t], ssy[t],
                    sm[t + off], ss[t + off], ssx[t + off], ssy[t + off]);
        __syncthreads();
    }
    if (t == 0) {
        float inv = 1.0f / ss[0];
        g_maxv[map] = sm[0];
        g_x[map]    = ssx[0] * inv;
        g_y[map]    = ssy[0] * inv;
    }
}

// ---------------- kernel 2: geometry (F matrices, scores, view weights) ----------------

__device__ __forceinline__ void inv3(const float* a, float* o) {
    float c00 = a[4]*a[8] - a[5]*a[7];
    float c01 = a[3]*a[8] - a[5]*a[6];
    float c02 = a[3]*a[7] - a[4]*a[6];
    float det = a[0]*c00 - a[1]*c01 + a[2]*c02;
    float id = 1.0f / det;
    o[0] =  c00 * id;
    o[1] = (a[2]*a[7] - a[1]*a[8]) * id;
    o[2] = (a[1]*a[5] - a[2]*a[4]) * id;
    o[3] = -c01 * id;
    o[4] = (a[0]*a[8] - a[2]*a[6]) * id;
    o[5] = (a[2]*a[3] - a[0]*a[5]) * id;
    o[6] =  c02 * id;
    o[7] = (a[1]*a[6] - a[0]*a[7]) * id;
    o[8] = (a[0]*a[4] - a[1]*a[3]) * id;
}

__device__ __forceinline__ void computeF(const float R[2][9], const float tt[2][3],
                                         const float iK[2][9], int vi, int vj, float* F) {
    // r = R_i @ R_j^T
    float r[9];
#pragma unroll
    for (int m = 0; m < 3; m++)
#pragma unroll
        for (int n = 0; n < 3; n++)
            r[m*3+n] = R[vi][m*3+0]*R[vj][n*3+0] + R[vi][m*3+1]*R[vj][n*3+1] + R[vi][m*3+2]*R[vj][n*3+2];
    // t = t_i - r @ t_j
    float tv[3];
#pragma unroll
    for (int m = 0; m < 3; m++)
        tv[m] = tt[vi][m] - (r[m*3+0]*tt[vj][0] + r[m*3+1]*tt[vj][1] + r[m*3+2]*tt[vj][2]);
    // M = skew(t) @ r
    float S[9] = { 0.f,   -tv[2],  tv[1],
                   tv[2],  0.f,   -tv[0],
                  -tv[1],  tv[0],  0.f };
    float M[9];
#pragma unroll
    for (int m = 0; m < 3; m++)
#pragma unroll
        for (int n = 0; n < 3; n++)
            M[m*3+n] = S[m*3+0]*r[n] + S[m*3+1]*r[3+n] + S[m*3+2]*r[6+n];
    // tmp = M @ iK_j
    float tmp[9];
#pragma unroll
    for (int p = 0; p < 3; p++)
#pragma unroll
        for (int l = 0; l < 3; l++)
            tmp[p*3+l] = M[p*3+0]*iK[vj][0*3+l] + M[p*3+1]*iK[vj][1*3+l] + M[p*3+2]*iK[vj][2*3+l];
    // F = iK_i^T @ tmp
#pragma unroll
    for (int m = 0; m < 3; m++)
#pragma unroll
        for (int l = 0; l < 3; l++)
            F[m*3+l] = iK[vi][0*3+m]*tmp[0*3+l] + iK[vi][1*3+m]*tmp[1*3+l] + iK[vi][2*3+m]*tmp[2*3+l];
}

__device__ __forceinline__ float epidist(const float* F, const float* a, const float* b) {
    float l0 = F[0]*b[0] + F[1]*b[1] + F[2]*b[2];
    float l1 = F[3]*b[0] + F[4]*b[1] + F[5]*b[2];
    float l2 = F[6]*b[0] + F[7]*b[1] + F[8]*b[2];
    float sc = a[0]*l0 + a[1]*l1 + a[2]*l2;
    float lp0 = F[0]*a[0] + F[3]*a[1] + F[6]*a[2];
    float lp1 = F[1]*a[0] + F[4]*a[1] + F[7]*a[2];
    float div = l0*l0 + l1*l1 + lp0*lp0 + lp1*lp1;
    return sqrtf(sc*sc / (div + EPSV));
}

__global__ void geom_kernel(const float* __restrict__ AP_K,
                            const float* __restrict__ AP_T,
                            const float* __restrict__ LAT_K,
                            const float* __restrict__ LAT_T) {
    int b = blockIdx.x;
    int k = threadIdx.x;  // 32 threads, joints 0..16 active at the end

    float K0[9], K1[9], T0[16], T1[16];
#pragma unroll
    for (int i = 0; i < 9; i++)  { K0[i] = AP_K[b*9 + i];  K1[i] = LAT_K[b*9 + i]; }
#pragma unroll
    for (int i = 0; i < 16; i++) { T0[i] = AP_T[b*16 + i]; T1[i] = LAT_T[b*16 + i]; }

    float R[2][9], tt[2][3];
#pragma unroll
    for (int m = 0; m < 3; m++) {
#pragma unroll
        for (int n = 0; n < 3; n++) {
            R[0][m*3+n] = T0[m*4+n];
            R[1][m*3+n] = T1[m*4+n];
        }
        tt[0][m] = T0[m*4+3];
        tt[1][m] = T1[m*4+3];
    }

    float iK[2][9];
    inv3(K0, iK[0]);
    inv3(K1, iK[1]);

    float F01[9], F10[9];
    computeF(R, tt, iK, 0, 1, F01);
    computeF(R, tt, iK, 1, 0, F10);

    if (k < JN) {
        int m0 = (b * 2) * JN + k;
        int m1 = m0 + JN;
        float x0 = g_x[m0], y0 = g_y[m0], mv0 = g_maxv[m0];
        float x1 = g_x[m1], y1 = g_y[m1], mv1 = g_maxv[m1];
        float i0[3] = { 4.f*x0, 4.f*y0, 1.f };
        float i1[3] = { 4.f*x1, 4.f*y1, 1.f };
        float d0 = epidist(F01, i0, i1);   // view 0 vs view 1
        float d1 = epidist(F10, i1, i0);   // view 1 vs view 0
        float s0 = mv0 - d0;
        float s1 = mv1 - d1;
        float mm = fmaxf(s0, s1);
        float e0 = __expf(s0 - mm);
        float e1 = __expf(s1 - mm);
        float inv = 1.0f / (e0 + e1);
        float den0 = (mv0 > 0.01f) ? mv0 : 1e6f;
        float den1 = (mv1 > 0.01f) ? mv1 : 1e6f;
        g_w[m0] = e0 * inv / den0;
        g_w[m1] = e1 * inv / den1;
    }
}

// ---------------- kernel 3: fuse heatmaps + second soft-argmax ----------------

__global__ void fuse_kernel(const float* __restrict__ hms, float* __restrict__ out) {
    int bj = blockIdx.x;          // b*17 + j
    int b = bj / JN;
    int j = bj % JN;
    int m0 = (b * 2) * JN + j;
    int m1 = m0 + JN;
    float w0 = g_w[m0];
    float w1 = g_w[m1];

    const float4* a = (const float4*)(hms + (size_t)m0 * HW);
    const float4* c = (const float4*)(hms + (size_t)m1 * HW);
    float4* o0 = (float4*)(out + IMG2_ELEMS + (size_t)m0 * HW);
    float4* o1 = (float4*)(out + IMG2_ELEMS + (size_t)m1 * HW);

    int t = threadIdx.x;
    float m = -1e30f, s = 0.f, sx = 0.f, sy = 0.f;

#pragma unroll
    for (int i = 0; i < 16; i++) {
        int i4 = t + i * 256;
        float4 va = a[i4];
        float4 vc = c[i4];
        float4 f;
        f.x = w0 * va.x + w1 * vc.x;
        f.y = w0 * va.y + w1 * vc.y;
        f.z = w0 * va.z + w1 * vc.z;
        f.w = w0 * va.w + w1 * vc.w;
        o0[i4] = f;
        o1[i4] = f;
        int base = i4 * 4;
        float hy = (float)(base >> 7);
        float wx = (float)(base & 127);
        online_upd(f.x, wx,       hy, m, s, sx, sy);
        online_upd(f.y, wx + 1.f, hy, m, s, sx, sy);
        online_upd(f.z, wx + 2.f, hy, m, s, sx, sy);
        online_upd(f.w, wx + 3.f, hy, m, s, sx, sy);
    }

    __shared__ float sm[256], ss[256], ssx[256], ssy[256];
    sm[t] = m; ss[t] = s; ssx[t] = sx; ssy[t] = sy;
    __syncthreads();
    for (int off = 128; off; off >>= 1) {
        if (t < off)
            combine(sm[t], ss[t], ssx[t], ssy[t],
                    sm[t + off], ss[t + off], ssx[t + off], ssy[t + off]);
        __syncthreads();
    }
    if (t == 0) {
        float inv = 1.0f / ss[0];
        float x2 = ssx[0] * inv;
        float y2 = ssy[0] * inv;
        // img2 layout (B, V, 2, J); identical for both views
#pragma unroll
        for (int v = 0; v < 2; v++) {
            int base = ((b * 2 + v) * 2) * JN + j;
            out[base]      = 4.0f * x2;
            out[base + JN] = 4.0f * y2;
        }
    }
}

// ---------------- launcher ----------------

extern "C" void kernel_launch(void* const* d_in, const int* in_sizes, int n_in,
                              void* d_out, int out_size) {
    const float* hms  = (const float*)d_in[0];
    const float* AP_K = (const float*)d_in[1];
    const float* AP_T = (const float*)d_in[2];
    const float* LK   = (const float*)d_in[3];
    const float* LT   = (const float*)d_in[4];
    float* out = (float*)d_out;

    stats_kernel<<<NMAPS, 256>>>(hms);
    geom_kernel<<<BN, 32>>>(AP_K, AP_T, LK, LT);
    fuse_kernel<<<NFUSE, 256>>>(hms, out);
}

// round 2
// speedup vs baseline: 1.1125x; 1.1125x over previous
#include <cuda_runtime.h>

#define BN 32
#define JN 17
#define HN 128
#define WN 128
#define HW (HN * WN)
#define NFUSE (BN * JN)                 // 544 blocks
#define IMG2_ELEMS (BN * 2 * 2 * JN)    // 2176
#define INV_T 20.0f
#define EPSV 1e-12f
#define NT 512
#define PT 8                            // float4 per thread per map

// ---------------- geometry helpers ----------------

__device__ __forceinline__ void inv3(const float* a, float* o) {
    float c00 = a[4]*a[8] - a[5]*a[7];
    float c01 = a[3]*a[8] - a[5]*a[6];
    float c02 = a[3]*a[7] - a[4]*a[6];
    float det = a[0]*c00 - a[1]*c01 + a[2]*c02;
    float id = 1.0f / det;
    o[0] =  c00 * id;
    o[1] = (a[2]*a[7] - a[1]*a[8]) * id;
    o[2] = (a[1]*a[5] - a[2]*a[4]) * id;
    o[3] = -c01 * id;
    o[4] = (a[0]*a[8] - a[2]*a[6]) * id;
    o[5] = (a[2]*a[3] - a[0]*a[5]) * id;
    o[6] =  c02 * id;
    o[7] = (a[1]*a[6] - a[0]*a[7]) * id;
    o[8] = (a[0]*a[4] - a[1]*a[3]) * id;
}

__device__ __forceinline__ void computeF(const float R[2][9], const float tt[2][3],
                                         const float iK[2][9], int vi, int vj, float* F) {
    float r[9];
#pragma unroll
    for (int m = 0; m < 3; m++)
#pragma unroll
        for (int n = 0; n < 3; n++)
            r[m*3+n] = R[vi][m*3+0]*R[vj][n*3+0] + R[vi][m*3+1]*R[vj][n*3+1] + R[vi][m*3+2]*R[vj][n*3+2];
    float tv[3];
#pragma unroll
    for (int m = 0; m < 3; m++)
        tv[m] = tt[vi][m] - (r[m*3+0]*tt[vj][0] + r[m*3+1]*tt[vj][1] + r[m*3+2]*tt[vj][2]);
    float S[9] = { 0.f,   -tv[2],  tv[1],
                   tv[2],  0.f,   -tv[0],
                  -tv[1],  tv[0],  0.f };
    float M[9];
#pragma unroll
    for (int m = 0; m < 3; m++)
#pragma unroll
        for (int n = 0; n < 3; n++)
            M[m*3+n] = S[m*3+0]*r[n] + S[m*3+1]*r[3+n] + S[m*3+2]*r[6+n];
    float tmp[9];
#pragma unroll
    for (int p = 0; p < 3; p++)
#pragma unroll
        for (int l = 0; l < 3; l++)
            tmp[p*3+l] = M[p*3+0]*iK[vj][0*3+l] + M[p*3+1]*iK[vj][1*3+l] + M[p*3+2]*iK[vj][2*3+l];
#pragma unroll
    for (int m = 0; m < 3; m++)
#pragma unroll
        for (int l = 0; l < 3; l++)
            F[m*3+l] = iK[vi][0*3+m]*tmp[0*3+l] + iK[vi][1*3+m]*tmp[1*3+l] + iK[vi][2*3+m]*tmp[2*3+l];
}

__device__ __forceinline__ float epidist(const float* F, const float* a, const float* b) {
    float l0 = F[0]*b[0] + F[1]*b[1] + F[2]*b[2];
    float l1 = F[3]*b[0] + F[4]*b[1] + F[5]*b[2];
    float l2 = F[6]*b[0] + F[7]*b[1] + F[8]*b[2];
    float sc = a[0]*l0 + a[1]*l1 + a[2]*l2;
    float lp0 = F[0]*a[0] + F[3]*a[1] + F[6]*a[2];
    float lp1 = F[1]*a[0] + F[4]*a[1] + F[7]*a[2];
    float div = l0*l0 + l1*l1 + lp0*lp0 + lp1*lp1;
    return sqrtf(sc*sc / (div + EPSV));
}

// ---------------- reduction helpers ----------------

__device__ __forceinline__ float warpMax(float v) {
#pragma unroll
    for (int o = 16; o; o >>= 1) v = fmaxf(v, __shfl_xor_sync(0xffffffffu, v, o));
    return v;
}
__device__ __forceinline__ float warpSum(float v) {
#pragma unroll
    for (int o = 16; o; o >>= 1) v += __shfl_xor_sync(0xffffffffu, v, o);
    return v;
}

// ---------------- the one kernel ----------------

__global__ void __launch_bounds__(NT)
fused_all(const float* __restrict__ hms,
          const float* __restrict__ AP_K, const float* __restrict__ AP_T,
          const float* __restrict__ LAT_K, const float* __restrict__ LAT_T,
          float* __restrict__ out) {
    int bj = blockIdx.x;
    int b = bj / JN;
    int j = bj % JN;
    int m0 = (b * 2) * JN + j;
    int m1 = m0 + JN;
    int t = threadIdx.x;
    int lane = t & 31, wid = t >> 5;

    __shared__ float sGeo[50];          // K0[9] K1[9] T0[16] T1[16]
    __shared__ float rA[16], rB[16], rC[16], rD[16], rE[16], rF[16];
    __shared__ float sW[2];

    // stage camera params into shared early (latency hides under heatmap loads)
    if (t < 9)       sGeo[t]      = AP_K[b*9 + t];
    else if (t < 18) sGeo[t]      = LAT_K[b*9 + t - 9];
    else if (t < 34) sGeo[t]      = AP_T[b*16 + t - 18];
    else if (t < 50) sGeo[t]      = LAT_T[b*16 + t - 34];

    const float4* a = (const float4*)(hms + (size_t)m0 * HW);
    const float4* c = (const float4*)(hms + (size_t)m1 * HW);

    float4 v0[PT], v1[PT];
#pragma unroll
    for (int i = 0; i < PT; i++) v0[i] = a[t + i * NT];
#pragma unroll
    for (int i = 0; i < PT; i++) v1[i] = c[t + i * NT];

    // ---- pass 1: max of each map ----
    float mx0 = -1e30f, mx1 = -1e30f;
#pragma unroll
    for (int i = 0; i < PT; i++) {
        mx0 = fmaxf(mx0, fmaxf(fmaxf(v0[i].x, v0[i].y), fmaxf(v0[i].z, v0[i].w)));
        mx1 = fmaxf(mx1, fmaxf(fmaxf(v1[i].x, v1[i].y), fmaxf(v1[i].z, v1[i].w)));
    }
    mx0 = warpMax(mx0); mx1 = warpMax(mx1);
    if (lane == 0) { rA[wid] = mx0; rB[wid] = mx1; }
    __syncthreads();
    float M0 = rA[0], M1 = rB[0];
#pragma unroll
    for (int i = 1; i < 16; i++) { M0 = fmaxf(M0, rA[i]); M1 = fmaxf(M1, rB[i]); }
    __syncthreads();

    // ---- pass 2: exp sums (branch-free) ----
    const float wx = (float)((4 * t) & 127);
    const float hy0 = (float)(t >> 5);
    float s0 = 0.f, sx0 = 0.f, sy0 = 0.f;
    float s1 = 0.f, sx1 = 0.f, sy1 = 0.f;
#pragma unroll
    for (int i = 0; i < PT; i++) {
        float hy = hy0 + 16.f * i;
        {
            float e0 = __expf((v0[i].x - M0) * INV_T);
            float e1 = __expf((v0[i].y - M0) * INV_T);
            float e2 = __expf((v0[i].z - M0) * INV_T);
            float e3 = __expf((v0[i].w - M0) * INV_T);
            float q = (e0 + e1) + (e2 + e3);
            s0 += q;
            sx0 += wx * q + (e1 + 2.f * e2 + 3.f * e3);
            sy0 += hy * q;
        }
        {
            float e0 = __expf((v1[i].x - M1) * INV_T);
            float e1 = __expf((v1[i].y - M1) * INV_T);
            float e2 = __expf((v1[i].z - M1) * INV_T);
            float e3 = __expf((v1[i].w - M1) * INV_T);
            float q = (e0 + e1) + (e2 + e3);
            s1 += q;
            sx1 += wx * q + (e1 + 2.f * e2 + 3.f * e3);
            sy1 += hy * q;
        }
    }
    s0 = warpSum(s0); sx0 = warpSum(sx0); sy0 = warpSum(sy0);
    s1 = warpSum(s1); sx1 = warpSum(sx1); sy1 = warpSum(sy1);
    if (lane == 0) {
        rA[wid] = s0; rB[wid] = sx0; rC[wid] = sy0;
        rD[wid] = s1; rE[wid] = sx1; rF[wid] = sy1;
    }
    __syncthreads();

    // ---- geometry + view weights on thread 0 ----
    if (t == 0) {
        float S0 = 0.f, SX0 = 0.f, SY0 = 0.f, S1 = 0.f, SX1 = 0.f, SY1 = 0.f;
#pragma unroll
        for (int i = 0; i < 16; i++) {
            S0 += rA[i]; SX0 += rB[i]; SY0 += rC[i];
            S1 += rD[i]; SX1 += rE[i]; SY1 += rF[i];
        }
        float x0 = SX0 / S0, y0 = SY0 / S0;
        float x1 = SX1 / S1, y1 = SY1 / S1;

        float R[2][9], tt[2][3], iK[2][9];
        inv3(&sGeo[0], iK[0]);
        inv3(&sGeo[9], iK[1]);
#pragma unroll
        for (int m = 0; m < 3; m++) {
#pragma unroll
            for (int n = 0; n < 3; n++) {
                R[0][m*3+n] = sGeo[18 + m*4 + n];
                R[1][m*3+n] = sGeo[34 + m*4 + n];
            }
            tt[0][m] = sGeo[18 + m*4 + 3];
            tt[1][m] = sGeo[34 + m*4 + 3];
        }
        float F01[9], F10[9];
        computeF(R, tt, iK, 0, 1, F01);
        computeF(R, tt, iK, 1, 0, F10);

        float i0[3] = { 4.f * x0, 4.f * y0, 1.f };
        float i1[3] = { 4.f * x1, 4.f * y1, 1.f };
        float d0 = epidist(F01, i0, i1);
        float d1 = epidist(F10, i1, i0);
        float sc0 = M0 - d0;
        float sc1 = M1 - d1;
        float mm = fmaxf(sc0, sc1);
        float e0 = __expf(sc0 - mm);
        float e1 = __expf(sc1 - mm);
        float inv = 1.0f / (e0 + e1);
        float den0 = (M0 > 0.01f) ? M0 : 1e6f;
        float den1 = (M1 > 0.01f) ? M1 : 1e6f;
        sW[0] = e0 * inv / den0;
        sW[1] = e1 * inv / den1;
    }
    __syncthreads();

    float w0 = sW[0];
    float w1 = sW[1];

    // ---- fuse in registers + write both views ----
    float4* o0 = (float4*)(out + IMG2_ELEMS + (size_t)m0 * HW);
    float4* o1 = (float4*)(out + IMG2_ELEMS + (size_t)m1 * HW);

    float fmx = -1e30f;
#pragma unroll
    for (int i = 0; i < PT; i++) {
        float4 f;
        f.x = w0 * v0[i].x + w1 * v1[i].x;
        f.y = w0 * v0[i].y + w1 * v1[i].y;
        f.z = w0 * v0[i].z + w1 * v1[i].z;
        f.w = w0 * v0[i].w + w1 * v1[i].w;
        o0[t + i * NT] = f;
        o1[t + i * NT] = f;
        v0[i] = f;
        fmx = fmaxf(fmx, fmaxf(fmaxf(f.x, f.y), fmaxf(f.z, f.w)));
    }
    fmx = warpMax(fmx);
    if (lane == 0) rA[wid] = fmx;
    __syncthreads();
    float FM = rA[0];
#pragma unroll
    for (int i = 1; i < 16; i++) FM = fmaxf(FM, rA[i]);
    __syncthreads();

    float fs = 0.f, fsx = 0.f, fsy = 0.f;
#pragma unroll
    for (int i = 0; i < PT; i++) {
        float hy = hy0 + 16.f * i;
        float e0 = __expf((v0[i].x - FM) * INV_T);
        float e1 = __expf((v0[i].y - FM) * INV_T);
        float e2 = __expf((v0[i].z - FM) * INV_T);
        float e3 = __expf((v0[i].w - FM) * INV_T);
        float q = (e0 + e1) + (e2 + e3);
        fs += q;
        fsx += wx * q + (e1 + 2.f * e2 + 3.f * e3);
        fsy += hy * q;
    }
    fs = warpSum(fs); fsx = warpSum(fsx); fsy = warpSum(fsy);
    if (lane == 0) { rA[wid] = fs; rB[wid] = fsx; rC[wid] = fsy; }
    __syncthreads();
    if (t == 0) {
        float S = 0.f, SX = 0.f, SY = 0.f;
#pragma unroll
        for (int i = 0; i < 16; i++) { S += rA[i]; SX += rB[i]; SY += rC[i]; }
        float x2 = 4.0f * SX / S;
        float y2 = 4.0f * SY / S;
#pragma unroll
        for (int v = 0; v < 2; v++) {
            int base = ((b * 2 + v) * 2) * JN + j;
            out[base]      = x2;
            out[base + JN] = y2;
        }
    }
}

// ---------------- launcher ----------------

extern "C" void kernel_launch(void* const* d_in, const int* in_sizes, int n_in,
                              void* d_out, int out_size) {
    const float* hms  = (const float*)d_in[0];
    const float* AP_K = (const float*)d_in[1];
    const float* AP_T = (const float*)d_in[2];
    const float* LK   = (const float*)d_in[3];
    const float* LT   = (const float*)d_in[4];
    float* out = (float*)d_out;

    fused_all<<<NFUSE, NT>>>(hms, AP_K, AP_T, LK, LT, out);
}